// round 5
// baseline (speedup 1.0000x reference)
#include <cuda_runtime.h>
#include <math.h>

#define NN 8192
#define DD 256
#define TK 5
#define TOPC 8

#define RT 64       // rows per CTA
#define JT 128      // j tile
#define JHALF 4096  // j range per CTA
#define KC 32       // k chunk for Fj
#define FI_PAD 264  // ≡8 mod 32 -> conflict-free LDS.64 frags
#define FJ_PAD 40   // ≡8 mod 32
#define S_PAD 136   // ≡8 mod 32

// ---------------- device scratch ----------------
__device__ float g_psum[32][DD];
__device__ float g_psq[32][DD];
__device__ float g_scale[DD];
__device__ float g_shift[DD];
__device__ float g_HnT[DD * NN];
__device__ float g_Hx[NN * DD];
__device__ float g_F1R[NN * DD];    // exact fp32 normalized rows
__device__ float g_F1tf[NN * DD];   // tf32-rounded
__device__ float g_G[NN * DD];
__device__ float g_cv[NN * 2 * TOPC];  // per (row, j-half) candidate dots
__device__ int   g_cj[NN * 2 * TOPC];
__device__ float g_tv[NN * TK];
__device__ int   g_ti[NN * TK];
__device__ float g_dinv[NN];

// ---------------- 1) batchnorm stats ----------------
__global__ void k_stats1(const float* __restrict__ H) {
    int b = blockIdx.x, t = threadIdx.x;
    const float* p = H + (size_t)b * 256 * DD + t;
    float s = 0.f, q = 0.f;
#pragma unroll 8
    for (int r = 0; r < 256; r++) {
        float x = p[(size_t)r * DD];
        s += x; q += x * x;
    }
    g_psum[b][t] = s;
    g_psq[b][t]  = q;
}

__global__ void k_stats2(const float* __restrict__ gamma, const float* __restrict__ beta) {
    int t = threadIdx.x;
    float s = 0.f, q = 0.f;
    for (int b = 0; b < 32; b++) { s += g_psum[b][t]; q += g_psq[b][t]; }
    float mu  = s * (1.f / NN);
    float var = q * (1.f / NN) - mu * mu;
    float sc  = gamma[t] * rsqrtf(var + 1e-5f);
    g_scale[t] = sc;
    g_shift[t] = beta[t] - mu * sc;
}

// ---------------- 3) Hn transposed [k][row] ----------------
__global__ void k_hnT(const float* __restrict__ H) {
    __shared__ float buf[32 * 257];
    int r0 = blockIdx.x * 32;
    int tid = threadIdx.x;
#pragma unroll
    for (int it = 0; it < 8; it++) {
        int e = it * 256 + tid;
        int r = e >> 6;
        int c = (e & 63) * 4;
        float4 h = *(const float4*)(H + (size_t)(r0 + r) * DD + c);
        buf[r * 257 + c + 0] = fmaf(h.x, g_scale[c + 0], g_shift[c + 0]);
        buf[r * 257 + c + 1] = fmaf(h.y, g_scale[c + 1], g_shift[c + 1]);
        buf[r * 257 + c + 2] = fmaf(h.z, g_scale[c + 2], g_shift[c + 2]);
        buf[r * 257 + c + 3] = fmaf(h.w, g_scale[c + 3], g_shift[c + 3]);
    }
    __syncthreads();
    int lane = tid & 31;
    int cbase = tid >> 5;
#pragma unroll
    for (int it = 0; it < 32; it++) {
        int c = cbase + it * 8;
        g_HnT[(size_t)c * NN + r0 + lane] = buf[lane * 257 + c];
    }
}

// ---------------- 4) GEMM: [Hx | G] ----------------
__global__ __launch_bounds__(256) void k_gemm(
    const float* __restrict__ Wt, const float* __restrict__ bt,
    const float* __restrict__ Wo, const float* __restrict__ bo) {
    __shared__ float As[64 * 64];
    __shared__ float Bs[64 * 64];
    int tid = threadIdx.x, tx = tid & 15, ty = tid >> 4;
    int i0 = blockIdx.x * 64;
    int by = blockIdx.y;
    const float* W    = (by < 4) ? Wt : Wo;
    const float* bias = (by < 4) ? bt : bo;
    float* C          = (by < 4) ? g_Hx : g_G;
    int n0 = (by & 3) * 64;

    float acc[4][4] = {};
    for (int kc = 0; kc < 256; kc += 64) {
#pragma unroll
        for (int it = 0; it < 4; it++) {
            int e = it * 256 + tid;
            int k = e >> 4, r4 = e & 15;
            float4 v = *(const float4*)(g_HnT + (size_t)(kc + k) * NN + i0 + r4 * 4);
            *(float4*)(As + k * 64 + r4 * 4) = v;
        }
#pragma unroll
        for (int it = 0; it < 4; it++) {
            int e = it * 256 + tid;
            int k = e >> 4, n4 = e & 15;
            float4 v = *(const float4*)(W + (size_t)(kc + k) * DD + n0 + n4 * 4);
            *(float4*)(Bs + k * 64 + n4 * 4) = v;
        }
        __syncthreads();
#pragma unroll 8
        for (int k = 0; k < 64; k++) {
            float4 a = *(const float4*)(As + k * 64 + ty * 4);
            float4 b = *(const float4*)(Bs + k * 64 + tx * 4);
            acc[0][0] += a.x * b.x; acc[0][1] += a.x * b.y; acc[0][2] += a.x * b.z; acc[0][3] += a.x * b.w;
            acc[1][0] += a.y * b.x; acc[1][1] += a.y * b.y; acc[1][2] += a.y * b.z; acc[1][3] += a.y * b.w;
            acc[2][0] += a.z * b.x; acc[2][1] += a.z * b.y; acc[2][2] += a.z * b.z; acc[2][3] += a.z * b.w;
            acc[3][0] += a.w * b.x; acc[3][1] += a.w * b.y; acc[3][2] += a.w * b.z; acc[3][3] += a.w * b.w;
        }
        __syncthreads();
    }
#pragma unroll
    for (int q = 0; q < 4; q++) {
        int r = i0 + ty * 4 + q;
#pragma unroll
        for (int p = 0; p < 4; p++) {
            int n = n0 + tx * 4 + p;
            C[(size_t)r * DD + n] = acc[q][p] + bias[n];
        }
    }
}

// ---------------- 5) normalize -> F1R + F1tf ----------------
__device__ __forceinline__ unsigned f2tf(float x) {
    unsigned r;
    asm("cvt.rna.tf32.f32 %0, %1;" : "=r"(r) : "f"(x));
    return r;
}

__global__ void k_norm() {
    int row = blockIdx.x * 8 + (threadIdx.x >> 5);
    int lane = threadIdx.x & 31;
    const float4* src = (const float4*)(g_Hx + (size_t)row * DD);
    float4 x0 = src[lane];
    float4 x1 = src[lane + 32];
    float s = x0.x * x0.x + x0.y * x0.y + x0.z * x0.z + x0.w * x0.w
            + x1.x * x1.x + x1.y * x1.y + x1.z * x1.z + x1.w * x1.w;
#pragma unroll
    for (int o = 16; o > 0; o >>= 1) s += __shfl_xor_sync(0xffffffffu, s, o);
    float inv = 1.f / fmaxf(sqrtf(s), 1e-12f);
    float4 y0 = make_float4(x0.x * inv, x0.y * inv, x0.z * inv, x0.w * inv);
    float4 y1 = make_float4(x1.x * inv, x1.y * inv, x1.z * inv, x1.w * inv);
    ((float4*)(g_F1R + (size_t)row * DD))[lane]      = y0;
    ((float4*)(g_F1R + (size_t)row * DD))[lane + 32] = y1;
    uint4 t0 = make_uint4(f2tf(y0.x), f2tf(y0.y), f2tf(y0.z), f2tf(y0.w));
    uint4 t1 = make_uint4(f2tf(y1.x), f2tf(y1.y), f2tf(y1.z), f2tf(y1.w));
    ((uint4*)(g_F1tf + (size_t)row * DD))[lane]      = t0;
    ((uint4*)(g_F1tf + (size_t)row * DD))[lane + 32] = t1;
}

__device__ __forceinline__ float affinity(float d) {
    d = fminf(fmaxf(d, -1.f), 1.f);
    float sam = acosf(d);
    float e = expf(-0.2f * sam);
    float a = 1.f / (1.f + expf(-e));
    return fmaxf(a, 0.1f);
}

__device__ __forceinline__ void mma_tf32(float c[4], const unsigned a[4], const unsigned b[2]) {
    asm volatile(
        "mma.sync.aligned.m16n8k8.row.col.f32.tf32.tf32.f32 "
        "{%0,%1,%2,%3}, {%4,%5,%6,%7}, {%8,%9}, {%0,%1,%2,%3};"
        : "+f"(c[0]), "+f"(c[1]), "+f"(c[2]), "+f"(c[3])
        : "r"(a[0]), "r"(a[1]), "r"(a[2]), "r"(a[3]), "r"(b[0]), "r"(b[1]));
}

// k-permutation within each 8-group: [0,4,1,5,2,6,3,7] -> pairs (t,t+4) adjacent
__device__ __forceinline__ int kperm(int km) {
    return (km & ~7) + ((km & 3) * 2 + ((km >> 2) & 1));
}

// ---------------- 6) main: tf32 S fused with approx top-8 (per j-half) ----------------
__global__ __launch_bounds__(256, 2) void k_maintc() {
    extern __shared__ float sm[];
    float* Fi = sm;                    // [64][264] full-K row panel, k-permuted
    float* Fj = sm + RT * FI_PAD;      // [128][40] one k-chunk, k-permuted
    float* Ss = Fj + JT * FJ_PAD;      // [32][136] half S tile

    int tid = threadIdx.x;
    int lane = tid & 31, w = tid >> 5;
    int wm = w & 1, wn = w >> 1;       // 2 x 4 warp grid over 64x128
    int gid = lane >> 2, tig = lane & 3;
    int bi = blockIdx.x >> 1, jh = blockIdx.x & 1;
    int i0 = bi * RT;
    int jbase = jh * JHALF;
    int srow = tid >> 3, ssub = tid & 7;  // scan: 8 threads per row (32 rows/half)

    // load Fi, k-permuted
#pragma unroll
    for (int it = 0; it < 16; it++) {
        int e = it * 256 + tid;
        int r = e >> 6, k = (e & 63) * 4;
        float4 v = *(const float4*)(g_F1tf + (size_t)(i0 + r) * DD + k);
        float* dst = Fi + r * FI_PAD;
        dst[kperm(k + 0)] = v.x;
        dst[kperm(k + 1)] = v.y;
        dst[kperm(k + 2)] = v.z;
        dst[kperm(k + 3)] = v.w;
    }

    float dv[2][TOPC]; int dj[2][TOPC];
#pragma unroll
    for (int h = 0; h < 2; h++)
#pragma unroll
        for (int m = 0; m < TOPC; m++) { dv[h][m] = -3.f; dj[h][m] = 0x7fffffff; }

    __syncthreads();

    for (int jt = 0; jt < JHALF / JT; jt++) {
        int j0 = jbase + jt * JT;
        float acc[2][4][4];
#pragma unroll
        for (int mi = 0; mi < 2; mi++)
#pragma unroll
            for (int ni = 0; ni < 4; ni++)
#pragma unroll
                for (int q = 0; q < 4; q++) acc[mi][ni][q] = 0.f;

        for (int kc = 0; kc < DD; kc += KC) {
            // load Fj chunk [128][32], k-permuted
#pragma unroll
            for (int it = 0; it < 4; it++) {
                int e = it * 256 + tid;
                int r = e >> 3, km = (e & 7) * 4;
                float4 v = *(const float4*)(g_F1tf + (size_t)(j0 + r) * DD + kc + km);
                float* dst = Fj + r * FJ_PAD;
                dst[kperm(km + 0)] = v.x;
                dst[kperm(km + 1)] = v.y;
                dst[kperm(km + 2)] = v.z;
                dst[kperm(km + 3)] = v.w;
            }
            __syncthreads();
#pragma unroll
            for (int k8 = 0; k8 < KC; k8 += 8) {
                unsigned a[2][4], b[4][2];
#pragma unroll
                for (int mi = 0; mi < 2; mi++) {
                    int r = wm * 32 + mi * 16 + gid;
                    float2 p0 = *(const float2*)(Fi + r * FI_PAD + kc + k8 + 2 * tig);
                    float2 p1 = *(const float2*)(Fi + (r + 8) * FI_PAD + kc + k8 + 2 * tig);
                    a[mi][0] = __float_as_uint(p0.x);
                    a[mi][1] = __float_as_uint(p1.x);
                    a[mi][2] = __float_as_uint(p0.y);
                    a[mi][3] = __float_as_uint(p1.y);
                }
#pragma unroll
                for (int ni = 0; ni < 4; ni++) {
                    int c = wn * 32 + ni * 8 + gid;
                    float2 pb = *(const float2*)(Fj + c * FJ_PAD + k8 + 2 * tig);
                    b[ni][0] = __float_as_uint(pb.x);
                    b[ni][1] = __float_as_uint(pb.y);
                }
#pragma unroll
                for (int mi = 0; mi < 2; mi++)
#pragma unroll
                    for (int ni = 0; ni < 4; ni++)
                        mma_tf32(acc[mi][ni], a[mi], b[ni]);
            }
            __syncthreads();
        }

        // stage + scan in two 32-row halves
#pragma unroll
        for (int h = 0; h < 2; h++) {
            if (wm == h) {
#pragma unroll
                for (int mi = 0; mi < 2; mi++) {
                    int r = mi * 16 + gid;
#pragma unroll
                    for (int ni = 0; ni < 4; ni++) {
                        int c = wn * 32 + ni * 8 + tig * 2;
                        *(float2*)(Ss + r * S_PAD + c)       = make_float2(acc[mi][ni][0], acc[mi][ni][1]);
                        *(float2*)(Ss + (r + 8) * S_PAD + c) = make_float2(acc[mi][ni][2], acc[mi][ni][3]);
                    }
                }
            }
            __syncthreads();
            // 8 threads per row, cols c = ii*8 + ssub ascending
#pragma unroll 4
            for (int ii = 0; ii < 16; ii++) {
                int c = ii * 8 + ssub;
                float v = Ss[srow * S_PAD + c];
                int jj = j0 + c;
                if (v > dv[h][TOPC - 1] || (v == dv[h][TOPC - 1] && jj < dj[h][TOPC - 1])) {
                    dv[h][TOPC - 1] = v; dj[h][TOPC - 1] = jj;
#pragma unroll
                    for (int m = TOPC - 1; m > 0; m--) {
                        bool sw = dv[h][m] > dv[h][m - 1] ||
                                  (dv[h][m] == dv[h][m - 1] && dj[h][m] < dj[h][m - 1]);
                        if (sw) {
                            float tf = dv[h][m]; dv[h][m] = dv[h][m - 1]; dv[h][m - 1] = tf;
                            int ti = dj[h][m]; dj[h][m] = dj[h][m - 1]; dj[h][m - 1] = ti;
                        }
                    }
                }
            }
            __syncthreads();
        }
    }

    // dump per-thread candidate lists (8 per thread per half) into smem, reuse Fi
    float* cv = Fi;                    // [64][64]
    int*   cj = (int*)(Fi + 64 * 64);  // [64][64]
    __syncthreads();
#pragma unroll
    for (int h = 0; h < 2; h++) {
        int lr = h * 32 + srow;
#pragma unroll
        for (int m = 0; m < TOPC; m++) {
            cv[lr * 64 + ssub * TOPC + m] = dv[h][m];
            cj[lr * 64 + ssub * TOPC + m] = dj[h][m];
        }
    }
    __syncthreads();

    if (tid < RT) {
        float mv[TOPC]; int mj[TOPC];
#pragma unroll
        for (int m = 0; m < TOPC; m++) { mv[m] = -3.f; mj[m] = 0x7fffffff; }
        for (int c = 0; c < 64; c++) {
            float v = cv[tid * 64 + c];
            int jj = cj[tid * 64 + c];
            if (v > mv[TOPC - 1] || (v == mv[TOPC - 1] && jj < mj[TOPC - 1])) {
                mv[TOPC - 1] = v; mj[TOPC - 1] = jj;
#pragma unroll
                for (int m = TOPC - 1; m > 0; m--) {
                    bool sw = mv[m] > mv[m - 1] || (mv[m] == mv[m - 1] && mj[m] < mj[m - 1]);
                    if (sw) {
                        float tf = mv[m]; mv[m] = mv[m - 1]; mv[m - 1] = tf;
                        int ti = mj[m]; mj[m] = mj[m - 1]; mj[m - 1] = ti;
                    }
                }
            }
        }
        int base = ((i0 + tid) * 2 + jh) * TOPC;
#pragma unroll
        for (int m = 0; m < TOPC; m++) {
            g_cv[base + m] = mv[m];
            g_cj[base + m] = mj[m];
        }
    }
}

// ---------------- 7) final: merge halves + exact fp32 rescue + A-level top-5 ----------------
__global__ void k_final() {
    int i = blockIdx.x * 256 + threadIdx.x;

    float mv[TOPC]; int mj[TOPC];
#pragma unroll
    for (int m = 0; m < TOPC; m++) { mv[m] = -3.f; mj[m] = 0x7fffffff; }
#pragma unroll
    for (int s = 0; s < 2 * TOPC; s++) {
        float v = g_cv[i * 2 * TOPC + s];
        int jj = g_cj[i * 2 * TOPC + s];
        if (v > mv[TOPC - 1] || (v == mv[TOPC - 1] && jj < mj[TOPC - 1])) {
            mv[TOPC - 1] = v; mj[TOPC - 1] = jj;
#pragma unroll
            for (int m = TOPC - 1; m > 0; m--) {
                bool sw = mv[m] > mv[m - 1] || (mv[m] == mv[m - 1] && mj[m] < mj[m - 1]);
                if (sw) {
                    float tf = mv[m]; mv[m] = mv[m - 1]; mv[m - 1] = tf;
                    int ti = mj[m]; mj[m] = mj[m - 1]; mj[m - 1] = ti;
                }
            }
        }
    }

    // exact fp32 dots (sequential-k chains)
    float ev[TOPC];
#pragma unroll
    for (int m = 0; m < TOPC; m++) ev[m] = 0.f;
    const float* ri = g_F1R + (size_t)i * DD;
    for (int k = 0; k < DD; k++) {
        float a = ri[k];
#pragma unroll
        for (int m = 0; m < TOPC; m++)
            ev[m] = fmaf(a, g_F1R[(size_t)mj[m] * DD + k], ev[m]);
    }

    // sort by (exact dot desc, idx asc)
#pragma unroll
    for (int m = 1; m < TOPC; m++) {
#pragma unroll
        for (int q = TOPC - 1; q >= 1; q--) {
            bool sw = (ev[q] > ev[q - 1]) || (ev[q] == ev[q - 1] && mj[q] < mj[q - 1]);
            if (sw) {
                float tf = ev[q]; ev[q] = ev[q - 1]; ev[q - 1] = tf;
                int ti = mj[q]; mj[q] = mj[q - 1]; mj[q - 1] = ti;
            }
        }
    }

    // A values + stable (A desc, idx asc) sort — matches lax.top_k ties
    float av[TOPC];
#pragma unroll
    for (int m = 0; m < TOPC; m++) av[m] = affinity(ev[m]);
#pragma unroll
    for (int m = 1; m < TOPC; m++) {
#pragma unroll
        for (int q = TOPC - 1; q >= 1; q--) {
            bool sw = (av[q] > av[q - 1]) || (av[q] == av[q - 1] && mj[q] < mj[q - 1]);
            if (sw) {
                float tf = av[q]; av[q] = av[q - 1]; av[q - 1] = tf;
                int ti = mj[q]; mj[q] = mj[q - 1]; mj[q - 1] = ti;
            }
        }
    }

    float rs = 0.f;
#pragma unroll
    for (int q = 0; q < TK; q++) {
        rs += av[q];
        g_tv[i * TK + q] = av[q];
        g_ti[i * TK + q] = mj[q];
    }
    g_dinv[i] = rsqrtf(rs);
}

// ---------------- 8) scatter sparse A ----------------
__global__ void k_scatterA(float* __restrict__ A) {
    int e = blockIdx.x * blockDim.x + threadIdx.x;
    if (e < NN * TK) {
        int row = e / TK;
        A[(size_t)row * NN + g_ti[e]] = g_tv[e];
    }
}

// ---------------- 9) out = leaky(A_hat @ G) ----------------
__global__ void k_out(float* __restrict__ out) {
    int i = blockIdx.x;
    int c4 = threadIdx.x;
    float di = g_dinv[i];
    float4 acc = make_float4(0.f, 0.f, 0.f, 0.f);
#pragma unroll
    for (int q = 0; q < TK; q++) {
        int j = g_ti[i * TK + q];
        float w = di * g_tv[i * TK + q] * g_dinv[j];
        float4 g = ((const float4*)(g_G + (size_t)j * DD))[c4];
        acc.x += w * g.x; acc.y += w * g.y; acc.z += w * g.z; acc.w += w * g.w;
    }
    acc.x = acc.x >= 0.f ? acc.x : 0.01f * acc.x;
    acc.y = acc.y >= 0.f ? acc.y : 0.01f * acc.y;
    acc.z = acc.z >= 0.f ? acc.z : 0.01f * acc.z;
    acc.w = acc.w >= 0.f ? acc.w : 0.01f * acc.w;
    ((float4*)(out + (size_t)i * DD))[c4] = acc;
}

// ---------------- launcher ----------------
extern "C" void kernel_launch(void* const* d_in, const int* in_sizes, int n_in,
                              void* d_out, int out_size) {
    const float* H     = (const float*)d_in[0];
    const float* gamma = (const float*)d_in[1];
    const float* beta  = (const float*)d_in[2];
    const float* Wt    = (const float*)d_in[3];
    const float* bt    = (const float*)d_in[4];
    const float* Wo    = (const float*)d_in[5];
    const float* bo    = (const float*)d_in[6];

    float* outbuf = (float*)d_out;
    const long long OUT_ND = (long long)NN * DD;
    const long long A_NN   = (long long)NN * NN;

    float* outp = nullptr;
    float* Ap   = nullptr;
    long long osz = (long long)out_size;
    if (osz == OUT_ND + A_NN)      { outp = outbuf; Ap = outbuf + OUT_ND; }
    else if (osz == A_NN)          { Ap = outbuf; }
    else if (osz == OUT_ND)        { outp = outbuf; }
    else                           { outp = outbuf; if (osz >= OUT_ND + A_NN) Ap = outbuf + OUT_ND; }

    size_t main_smem = (size_t)(RT * FI_PAD + JT * FJ_PAD + 32 * S_PAD) * sizeof(float);
    cudaFuncSetAttribute(k_maintc, cudaFuncAttributeMaxDynamicSharedMemorySize, (int)main_smem);

    k_stats1<<<32, 256>>>(H);
    k_stats2<<<1, 256>>>(gamma, beta);
    k_hnT<<<NN / 32, 256>>>(H);
    {
        dim3 g(NN / 64, 8);
        k_gemm<<<g, 256>>>(Wt, bt, Wo, bo);
    }
    k_norm<<<NN / 8, 256>>>();
    k_maintc<<<(NN / RT) * 2, 256, main_smem>>>();
    k_final<<<NN / 256, 256>>>();

    if (Ap) {
        cudaMemsetAsync(Ap, 0, (size_t)A_NN * sizeof(float), 0);
        k_scatterA<<<(NN * TK + 255) / 256, 256>>>(Ap);
    }
    if (outp) {
        k_out<<<NN, 64>>>(outp);
    }
}

// round 6
// speedup vs baseline: 1.2760x; 1.2760x over previous
#include <cuda_runtime.h>
#include <math.h>

#define NN 8192
#define DD 256
#define TK 5
#define TOPC 8

#define RT 64       // rows per CTA
#define JT 256      // j tile
#define KC 32       // k chunk for Fj (double-buffered)
#define NCH (DD / KC)
#define NJT (NN / JT)
#define FI_PAD 260  // ≡4 mod 32 -> conflict-free frag loads
#define FJ_PAD 36   // ≡4 mod 32
#define S_PAD 264   // ≡8 mod 32

// ---------------- device scratch ----------------
__device__ float g_psum[32][DD];
__device__ float g_psq[32][DD];
__device__ float g_scale[DD];
__device__ float g_shift[DD];
__device__ float g_HnT[DD * NN];
__device__ float g_Hx[NN * DD];
__device__ float g_F1R[NN * DD];    // exact fp32 normalized rows
__device__ float g_F1tf[NN * DD];   // tf32-rounded
__device__ float g_G[NN * DD];
__device__ float g_tv[NN * TK];
__device__ int   g_ti[NN * TK];
__device__ float g_dinv[NN];

// ---------------- 1) batchnorm stats ----------------
__global__ void k_stats1(const float* __restrict__ H) {
    int b = blockIdx.x, t = threadIdx.x;
    const float* p = H + (size_t)b * 256 * DD + t;
    float s = 0.f, q = 0.f;
#pragma unroll 8
    for (int r = 0; r < 256; r++) {
        float x = p[(size_t)r * DD];
        s += x; q += x * x;
    }
    g_psum[b][t] = s;
    g_psq[b][t]  = q;
}

__global__ void k_stats2(const float* __restrict__ gamma, const float* __restrict__ beta) {
    int t = threadIdx.x;
    float s = 0.f, q = 0.f;
    for (int b = 0; b < 32; b++) { s += g_psum[b][t]; q += g_psq[b][t]; }
    float mu  = s * (1.f / NN);
    float var = q * (1.f / NN) - mu * mu;
    float sc  = gamma[t] * rsqrtf(var + 1e-5f);
    g_scale[t] = sc;
    g_shift[t] = beta[t] - mu * sc;
}

// ---------------- 3) Hn transposed [k][row] ----------------
__global__ void k_hnT(const float* __restrict__ H) {
    __shared__ float buf[32 * 257];
    int r0 = blockIdx.x * 32;
    int tid = threadIdx.x;
#pragma unroll
    for (int it = 0; it < 8; it++) {
        int e = it * 256 + tid;
        int r = e >> 6;
        int c = (e & 63) * 4;
        float4 h = *(const float4*)(H + (size_t)(r0 + r) * DD + c);
        buf[r * 257 + c + 0] = fmaf(h.x, g_scale[c + 0], g_shift[c + 0]);
        buf[r * 257 + c + 1] = fmaf(h.y, g_scale[c + 1], g_shift[c + 1]);
        buf[r * 257 + c + 2] = fmaf(h.z, g_scale[c + 2], g_shift[c + 2]);
        buf[r * 257 + c + 3] = fmaf(h.w, g_scale[c + 3], g_shift[c + 3]);
    }
    __syncthreads();
    int lane = tid & 31;
    int cbase = tid >> 5;
#pragma unroll
    for (int it = 0; it < 32; it++) {
        int c = cbase + it * 8;
        g_HnT[(size_t)c * NN + r0 + lane] = buf[lane * 257 + c];
    }
}

// ---------------- 4) GEMM: [Hx | G] ----------------
__global__ __launch_bounds__(256) void k_gemm(
    const float* __restrict__ Wt, const float* __restrict__ bt,
    const float* __restrict__ Wo, const float* __restrict__ bo) {
    __shared__ float As[64 * 64];
    __shared__ float Bs[64 * 64];
    int tid = threadIdx.x, tx = tid & 15, ty = tid >> 4;
    int i0 = blockIdx.x * 64;
    int by = blockIdx.y;
    const float* W    = (by < 4) ? Wt : Wo;
    const float* bias = (by < 4) ? bt : bo;
    float* C          = (by < 4) ? g_Hx : g_G;
    int n0 = (by & 3) * 64;

    float acc[4][4] = {};
    for (int kc = 0; kc < 256; kc += 64) {
#pragma unroll
        for (int it = 0; it < 4; it++) {
            int e = it * 256 + tid;
            int k = e >> 4, r4 = e & 15;
            float4 v = *(const float4*)(g_HnT + (size_t)(kc + k) * NN + i0 + r4 * 4);
            *(float4*)(As + k * 64 + r4 * 4) = v;
        }
#pragma unroll
        for (int it = 0; it < 4; it++) {
            int e = it * 256 + tid;
            int k = e >> 4, n4 = e & 15;
            float4 v = *(const float4*)(W + (size_t)(kc + k) * DD + n0 + n4 * 4);
            *(float4*)(Bs + k * 64 + n4 * 4) = v;
        }
        __syncthreads();
#pragma unroll 8
        for (int k = 0; k < 64; k++) {
            float4 a = *(const float4*)(As + k * 64 + ty * 4);
            float4 b = *(const float4*)(Bs + k * 64 + tx * 4);
            acc[0][0] += a.x * b.x; acc[0][1] += a.x * b.y; acc[0][2] += a.x * b.z; acc[0][3] += a.x * b.w;
            acc[1][0] += a.y * b.x; acc[1][1] += a.y * b.y; acc[1][2] += a.y * b.z; acc[1][3] += a.y * b.w;
            acc[2][0] += a.z * b.x; acc[2][1] += a.z * b.y; acc[2][2] += a.z * b.z; acc[2][3] += a.z * b.w;
            acc[3][0] += a.w * b.x; acc[3][1] += a.w * b.y; acc[3][2] += a.w * b.z; acc[3][3] += a.w * b.w;
        }
        __syncthreads();
    }
#pragma unroll
    for (int q = 0; q < 4; q++) {
        int r = i0 + ty * 4 + q;
#pragma unroll
        for (int p = 0; p < 4; p++) {
            int n = n0 + tx * 4 + p;
            C[(size_t)r * DD + n] = acc[q][p] + bias[n];
        }
    }
}

// ---------------- 5) normalize -> F1R + F1tf ----------------
__device__ __forceinline__ unsigned f2tf(float x) {
    unsigned r;
    asm("cvt.rna.tf32.f32 %0, %1;" : "=r"(r) : "f"(x));
    return r;
}

__global__ void k_norm() {
    int row = blockIdx.x * 8 + (threadIdx.x >> 5);
    int lane = threadIdx.x & 31;
    const float4* src = (const float4*)(g_Hx + (size_t)row * DD);
    float4 x0 = src[lane];
    float4 x1 = src[lane + 32];
    float s = x0.x * x0.x + x0.y * x0.y + x0.z * x0.z + x0.w * x0.w
            + x1.x * x1.x + x1.y * x1.y + x1.z * x1.z + x1.w * x1.w;
#pragma unroll
    for (int o = 16; o > 0; o >>= 1) s += __shfl_xor_sync(0xffffffffu, s, o);
    float inv = 1.f / fmaxf(sqrtf(s), 1e-12f);
    float4 y0 = make_float4(x0.x * inv, x0.y * inv, x0.z * inv, x0.w * inv);
    float4 y1 = make_float4(x1.x * inv, x1.y * inv, x1.z * inv, x1.w * inv);
    ((float4*)(g_F1R + (size_t)row * DD))[lane]      = y0;
    ((float4*)(g_F1R + (size_t)row * DD))[lane + 32] = y1;
    uint4 t0 = make_uint4(f2tf(y0.x), f2tf(y0.y), f2tf(y0.z), f2tf(y0.w));
    uint4 t1 = make_uint4(f2tf(y1.x), f2tf(y1.y), f2tf(y1.z), f2tf(y1.w));
    ((uint4*)(g_F1tf + (size_t)row * DD))[lane]      = t0;
    ((uint4*)(g_F1tf + (size_t)row * DD))[lane + 32] = t1;
}

__device__ __forceinline__ float affinity(float d) {
    d = fminf(fmaxf(d, -1.f), 1.f);
    float sam = acosf(d);
    float e = expf(-0.2f * sam);
    float a = 1.f / (1.f + expf(-e));
    return fmaxf(a, 0.1f);
}

__device__ __forceinline__ void mma_tf32(float c[4], const unsigned a[4], const unsigned b[2]) {
    asm volatile(
        "mma.sync.aligned.m16n8k8.row.col.f32.tf32.tf32.f32 "
        "{%0,%1,%2,%3}, {%4,%5,%6,%7}, {%8,%9}, {%0,%1,%2,%3};"
        : "+f"(c[0]), "+f"(c[1]), "+f"(c[2]), "+f"(c[3])
        : "r"(a[0]), "r"(a[1]), "r"(a[2]), "r"(a[3]), "r"(b[0]), "r"(b[1]));
}

__device__ __forceinline__ void cp16(float* dst_smem, const float* src_gmem) {
    unsigned d = (unsigned)__cvta_generic_to_shared(dst_smem);
    asm volatile("cp.async.cg.shared.global [%0], [%1], 16;" :: "r"(d), "l"(src_gmem));
}

// ---------------- 6) main: tf32 S, cp.async double-buffered, fused top-8 + exact rescue ----------------
__global__ __launch_bounds__(256, 1) void k_maintc() {
    extern __shared__ float sm[];
    float* Fi  = sm;                       // [64][260] full-K row panel
    float* FjB = sm + RT * FI_PAD;         // 2 x [256][36] k-chunk double buffer
    float* Ss  = FjB + 2 * JT * FJ_PAD;    // [64][264] staged S tile

    int tid = threadIdx.x;
    int lane = tid & 31, w = tid >> 5;
    int wm = w & 1, wn = w >> 1;           // 2 x 4 warps over 64 x 256
    int gid = lane >> 2, tig = lane & 3;
    int i0 = blockIdx.x * RT;
    int srow = tid >> 2, ssub = tid & 3;   // scan: 4 threads per row

    // load Fi full K (one-time)
#pragma unroll
    for (int it = 0; it < 16; it++) {
        int e = it * 256 + tid;
        int r = e >> 6, k4 = e & 63;
        float4 v = *(const float4*)(g_F1tf + (size_t)(i0 + r) * DD + k4 * 4);
        *(float4*)(Fi + r * FI_PAD + k4 * 4) = v;
    }

    float dv[TOPC]; int dj[TOPC];
#pragma unroll
    for (int m = 0; m < TOPC; m++) { dv[m] = -3.f; dj[m] = 0x7fffffff; }

    // issue chunk 0 of j-tile 0 into buffer 0
    {
        float* dst = FjB;
#pragma unroll
        for (int it = 0; it < 8; it++) {
            int e = it * 256 + tid;
            int r = e >> 3, k4 = (e & 7) * 4;
            cp16(dst + r * FJ_PAD + k4, g_F1tf + (size_t)r * DD + k4);
        }
        asm volatile("cp.async.commit_group;");
    }
    __syncthreads();

    for (int jt = 0; jt < NJT; jt++) {
        int j0 = jt * JT;
        float acc[2][8][4];
#pragma unroll
        for (int mi = 0; mi < 2; mi++)
#pragma unroll
            for (int ni = 0; ni < 8; ni++)
#pragma unroll
                for (int q = 0; q < 4; q++) acc[mi][ni][q] = 0.f;

        for (int ch = 0; ch < NCH; ch++) {
            // issue next chunk (possibly next j-tile's chunk 0)
            bool have_next = (jt * NCH + ch + 1) < (NJT * NCH);
            if (have_next) {
                int gnext = jt * NCH + ch + 1;
                int njt = gnext >> 3, nch = gnext & 7;
                int nj0 = njt * JT;
                float* dst = FjB + (gnext & 1) * JT * FJ_PAD;
#pragma unroll
                for (int it = 0; it < 8; it++) {
                    int e = it * 256 + tid;
                    int r = e >> 3, k4 = (e & 7) * 4;
                    cp16(dst + r * FJ_PAD + k4,
                         g_F1tf + (size_t)(nj0 + r) * DD + nch * KC + k4);
                }
                asm volatile("cp.async.commit_group;");
                asm volatile("cp.async.wait_group 1;");
            } else {
                asm volatile("cp.async.wait_group 0;");
            }
            __syncthreads();

            const float* Fj = FjB + ((jt * NCH + ch) & 1) * JT * FJ_PAD;
#pragma unroll
            for (int k8 = 0; k8 < KC; k8 += 8) {
                int kA = ch * KC + k8 + tig;
                int kB = k8 + tig;
                unsigned a[2][4], b[8][2];
#pragma unroll
                for (int mi = 0; mi < 2; mi++) {
                    int r = wm * 32 + mi * 16 + gid;
                    a[mi][0] = __float_as_uint(Fi[r * FI_PAD + kA]);
                    a[mi][1] = __float_as_uint(Fi[(r + 8) * FI_PAD + kA]);
                    a[mi][2] = __float_as_uint(Fi[r * FI_PAD + kA + 4]);
                    a[mi][3] = __float_as_uint(Fi[(r + 8) * FI_PAD + kA + 4]);
                }
#pragma unroll
                for (int ni = 0; ni < 8; ni++) {
                    int c = wn * 64 + ni * 8 + gid;
                    b[ni][0] = __float_as_uint(Fj[c * FJ_PAD + kB]);
                    b[ni][1] = __float_as_uint(Fj[c * FJ_PAD + kB + 4]);
                }
#pragma unroll
                for (int mi = 0; mi < 2; mi++)
#pragma unroll
                    for (int ni = 0; ni < 8; ni++)
                        mma_tf32(acc[mi][ni], a[mi], b[ni]);
            }
            __syncthreads();
        }

        // stage S tile (64 x 256)
#pragma unroll
        for (int mi = 0; mi < 2; mi++) {
            int r = wm * 32 + mi * 16 + gid;
#pragma unroll
            for (int ni = 0; ni < 8; ni++) {
                int c = wn * 64 + ni * 8 + tig * 2;
                *(float2*)(Ss + r * S_PAD + c)       = make_float2(acc[mi][ni][0], acc[mi][ni][1]);
                *(float2*)(Ss + (r + 8) * S_PAD + c) = make_float2(acc[mi][ni][2], acc[mi][ni][3]);
            }
        }
        __syncthreads();

        // scan: 4 threads/row, cols c = ii*4 + ssub ascending
#pragma unroll 8
        for (int ii = 0; ii < 64; ii++) {
            int c = ii * 4 + ssub;
            float v = Ss[srow * S_PAD + c];
            int jj = j0 + c;
            if (v > dv[TOPC - 1] || (v == dv[TOPC - 1] && jj < dj[TOPC - 1])) {
                dv[TOPC - 1] = v; dj[TOPC - 1] = jj;
#pragma unroll
                for (int m = TOPC - 1; m > 0; m--) {
                    bool sw = dv[m] > dv[m - 1] || (dv[m] == dv[m - 1] && dj[m] < dj[m - 1]);
                    if (sw) {
                        float tf = dv[m]; dv[m] = dv[m - 1]; dv[m - 1] = tf;
                        int ti = dj[m]; dj[m] = dj[m - 1]; dj[m - 1] = ti;
                    }
                }
            }
        }
        __syncthreads();
    }

    // ---- merge 4 scan-threads per row, then exact fp32 rescue ----
    float* cv = Ss;                   // [64][32]
    int*   cj = (int*)(Ss + 64 * 32); // [64][32]
#pragma unroll
    for (int m = 0; m < TOPC; m++) {
        cv[srow * 32 + ssub * TOPC + m] = dv[m];
        cj[srow * 32 + ssub * TOPC + m] = dj[m];
    }
    __syncthreads();

    if (tid < RT) {
        int i = i0 + tid;
        float mv[TOPC]; int mj[TOPC];
#pragma unroll
        for (int m = 0; m < TOPC; m++) { mv[m] = -3.f; mj[m] = 0x7fffffff; }
        for (int c = 0; c < 32; c++) {
            float v = cv[tid * 32 + c];
            int jj = cj[tid * 32 + c];
            if (v > mv[TOPC - 1] || (v == mv[TOPC - 1] && jj < mj[TOPC - 1])) {
                mv[TOPC - 1] = v; mj[TOPC - 1] = jj;
#pragma unroll
                for (int m = TOPC - 1; m > 0; m--) {
                    bool sw = mv[m] > mv[m - 1] || (mv[m] == mv[m - 1] && mj[m] < mj[m - 1]);
                    if (sw) {
                        float tf = mv[m]; mv[m] = mv[m - 1]; mv[m - 1] = tf;
                        int ti = mj[m]; mj[m] = mj[m - 1]; mj[m - 1] = ti;
                    }
                }
            }
        }

        // exact fp32 dots (sequential-k chains, identical to R2/R4 passing path)
        float ev[TOPC];
#pragma unroll
        for (int m = 0; m < TOPC; m++) ev[m] = 0.f;
        const float* ri = g_F1R + (size_t)i * DD;
        for (int k = 0; k < DD; k++) {
            float a = ri[k];
#pragma unroll
            for (int m = 0; m < TOPC; m++)
                ev[m] = fmaf(a, g_F1R[(size_t)mj[m] * DD + k], ev[m]);
        }

        // sort by (exact dot desc, idx asc)
#pragma unroll
        for (int m = 1; m < TOPC; m++) {
#pragma unroll
            for (int q = TOPC - 1; q >= 1; q--) {
                bool sw = (ev[q] > ev[q - 1]) || (ev[q] == ev[q - 1] && mj[q] < mj[q - 1]);
                if (sw) {
                    float tf = ev[q]; ev[q] = ev[q - 1]; ev[q - 1] = tf;
                    int ti = mj[q]; mj[q] = mj[q - 1]; mj[q - 1] = ti;
                }
            }
        }

        // A values + stable (A desc, idx asc) sort — matches lax.top_k ties
        float av[TOPC];
#pragma unroll
        for (int m = 0; m < TOPC; m++) av[m] = affinity(ev[m]);
#pragma unroll
        for (int m = 1; m < TOPC; m++) {
#pragma unroll
            for (int q = TOPC - 1; q >= 1; q--) {
                bool sw = (av[q] > av[q - 1]) || (av[q] == av[q - 1] && mj[q] < mj[q - 1]);
                if (sw) {
                    float tf = av[q]; av[q] = av[q - 1]; av[q - 1] = tf;
                    int ti = mj[q]; mj[q] = mj[q - 1]; mj[q - 1] = ti;
                }
            }
        }

        float rs = 0.f;
#pragma unroll
        for (int q = 0; q < TK; q++) {
            rs += av[q];
            g_tv[i * TK + q] = av[q];
            g_ti[i * TK + q] = mj[q];
        }
        g_dinv[i] = rsqrtf(rs);
    }
}

// ---------------- 7) scatter sparse A ----------------
__global__ void k_scatterA(float* __restrict__ A) {
    int e = blockIdx.x * blockDim.x + threadIdx.x;
    if (e < NN * TK) {
        int row = e / TK;
        A[(size_t)row * NN + g_ti[e]] = g_tv[e];
    }
}

// ---------------- 8) out = leaky(A_hat @ G) ----------------
__global__ void k_out(float* __restrict__ out) {
    int i = blockIdx.x;
    int c4 = threadIdx.x;
    float di = g_dinv[i];
    float4 acc = make_float4(0.f, 0.f, 0.f, 0.f);
#pragma unroll
    for (int q = 0; q < TK; q++) {
        int j = g_ti[i * TK + q];
        float w = di * g_tv[i * TK + q] * g_dinv[j];
        float4 g = ((const float4*)(g_G + (size_t)j * DD))[c4];
        acc.x += w * g.x; acc.y += w * g.y; acc.z += w * g.z; acc.w += w * g.w;
    }
    acc.x = acc.x >= 0.f ? acc.x : 0.01f * acc.x;
    acc.y = acc.y >= 0.f ? acc.y : 0.01f * acc.y;
    acc.z = acc.z >= 0.f ? acc.z : 0.01f * acc.z;
    acc.w = acc.w >= 0.f ? acc.w : 0.01f * acc.w;
    ((float4*)(out + (size_t)i * DD))[c4] = acc;
}

// ---------------- launcher ----------------
extern "C" void kernel_launch(void* const* d_in, const int* in_sizes, int n_in,
                              void* d_out, int out_size) {
    const float* H     = (const float*)d_in[0];
    const float* gamma = (const float*)d_in[1];
    const float* beta  = (const float*)d_in[2];
    const float* Wt    = (const float*)d_in[3];
    const float* bt    = (const float*)d_in[4];
    const float* Wo    = (const float*)d_in[5];
    const float* bo    = (const float*)d_in[6];

    float* outbuf = (float*)d_out;
    const long long OUT_ND = (long long)NN * DD;
    const long long A_NN   = (long long)NN * NN;

    float* outp = nullptr;
    float* Ap   = nullptr;
    long long osz = (long long)out_size;
    if (osz == OUT_ND + A_NN)      { outp = outbuf; Ap = outbuf + OUT_ND; }
    else if (osz == A_NN)          { Ap = outbuf; }
    else if (osz == OUT_ND)        { outp = outbuf; }
    else                           { outp = outbuf; if (osz >= OUT_ND + A_NN) Ap = outbuf + OUT_ND; }

    size_t main_smem = (size_t)(RT * FI_PAD + 2 * JT * FJ_PAD + RT * S_PAD) * sizeof(float);
    cudaFuncSetAttribute(k_maintc, cudaFuncAttributeMaxDynamicSharedMemorySize, (int)main_smem);

    k_stats1<<<32, 256>>>(H);
    k_stats2<<<1, 256>>>(gamma, beta);
    k_hnT<<<NN / 32, 256>>>(H);
    {
        dim3 g(NN / 64, 8);
        k_gemm<<<g, 256>>>(Wt, bt, Wo, bo);
    }
    k_norm<<<NN / 8, 256>>>();
    k_maintc<<<NN / RT, 256, main_smem>>>();

    if (Ap) {
        cudaMemsetAsync(Ap, 0, (size_t)A_NN * sizeof(float), 0);
        k_scatterA<<<(NN * TK + 255) / 256, 256>>>(Ap);
    }
    if (outp) {
        k_out<<<NN, 64>>>(outp);
    }
}

// round 8
// speedup vs baseline: 1.5607x; 1.2231x over previous
#include <cuda_runtime.h>
#include <cuda_bf16.h>
#include <math.h>

typedef unsigned int u32;

#define NN 8192
#define DD 256
#define TK 5
#define TOPC 8

#define RT 64        // rows per CTA
#define JT 256       // j tile
#define KC 64        // k chunk (bf16) for Fj
#define NCH (DD / KC)     // 4
#define NJT (NN / JT)     // 32
#define FI_PITCH 528      // bytes/row, 33*16 -> ldmatrix conflict-free
#define FJ_PITCH 144      // bytes/row, 9*16  -> ldmatrix conflict-free
#define FI_BYTES (RT * FI_PITCH)       // 33792
#define FJ_BYTES (JT * FJ_PITCH)       // 36864
#define S_PAD 264

// ---------------- device scratch ----------------
__device__ float g_psum[32][DD];
__device__ float g_psq[32][DD];
__device__ float g_scale[DD];
__device__ float g_shift[DD];
__device__ float g_HnT[DD * NN];
__device__ float g_Hx[NN * DD];
__device__ float g_F1R[NN * DD];            // exact fp32 normalized rows
__device__ __nv_bfloat16 g_F1bf[NN * DD];   // bf16 rows (mma operands)
__device__ float g_G[NN * DD];
__device__ float g_tv[NN * TK];
__device__ int   g_ti[NN * TK];
__device__ float g_dinv[NN];

// ---------------- 1) batchnorm stats ----------------
__global__ void k_stats1(const float* __restrict__ H) {
    int b = blockIdx.x, t = threadIdx.x;
    const float* p = H + (size_t)b * 256 * DD + t;
    float s = 0.f, q = 0.f;
#pragma unroll 8
    for (int r = 0; r < 256; r++) {
        float x = p[(size_t)r * DD];
        s += x; q += x * x;
    }
    g_psum[b][t] = s;
    g_psq[b][t]  = q;
}

__global__ void k_stats2(const float* __restrict__ gamma, const float* __restrict__ beta) {
    int t = threadIdx.x;
    float s = 0.f, q = 0.f;
    for (int b = 0; b < 32; b++) { s += g_psum[b][t]; q += g_psq[b][t]; }
    float mu  = s * (1.f / NN);
    float var = q * (1.f / NN) - mu * mu;
    float sc  = gamma[t] * rsqrtf(var + 1e-5f);
    g_scale[t] = sc;
    g_shift[t] = beta[t] - mu * sc;
}

// ---------------- 3) Hn transposed [k][row] ----------------
__global__ void k_hnT(const float* __restrict__ H) {
    __shared__ float buf[32 * 257];
    int r0 = blockIdx.x * 32;
    int tid = threadIdx.x;
#pragma unroll
    for (int it = 0; it < 8; it++) {
        int e = it * 256 + tid;
        int r = e >> 6;
        int c = (e & 63) * 4;
        float4 h = *(const float4*)(H + (size_t)(r0 + r) * DD + c);
        buf[r * 257 + c + 0] = fmaf(h.x, g_scale[c + 0], g_shift[c + 0]);
        buf[r * 257 + c + 1] = fmaf(h.y, g_scale[c + 1], g_shift[c + 1]);
        buf[r * 257 + c + 2] = fmaf(h.z, g_scale[c + 2], g_shift[c + 2]);
        buf[r * 257 + c + 3] = fmaf(h.w, g_scale[c + 3], g_shift[c + 3]);
    }
    __syncthreads();
    int lane = tid & 31;
    int cbase = tid >> 5;
#pragma unroll
    for (int it = 0; it < 32; it++) {
        int c = cbase + it * 8;
        g_HnT[(size_t)c * NN + r0 + lane] = buf[lane * 257 + c];
    }
}

// ---------------- 4) GEMM: [Hx | G] ----------------
__global__ __launch_bounds__(256) void k_gemm(
    const float* __restrict__ Wt, const float* __restrict__ bt,
    const float* __restrict__ Wo, const float* __restrict__ bo) {
    __shared__ float As[64 * 64];
    __shared__ float Bs[64 * 64];
    int tid = threadIdx.x, tx = tid & 15, ty = tid >> 4;
    int i0 = blockIdx.x * 64;
    int by = blockIdx.y;
    const float* W    = (by < 4) ? Wt : Wo;
    const float* bias = (by < 4) ? bt : bo;
    float* C          = (by < 4) ? g_Hx : g_G;
    int n0 = (by & 3) * 64;

    float acc[4][4] = {};
    for (int kc = 0; kc < 256; kc += 64) {
#pragma unroll
        for (int it = 0; it < 4; it++) {
            int e = it * 256 + tid;
            int k = e >> 4, r4 = e & 15;
            float4 v = *(const float4*)(g_HnT + (size_t)(kc + k) * NN + i0 + r4 * 4);
            *(float4*)(As + k * 64 + r4 * 4) = v;
        }
#pragma unroll
        for (int it = 0; it < 4; it++) {
            int e = it * 256 + tid;
            int k = e >> 4, n4 = e & 15;
            float4 v = *(const float4*)(W + (size_t)(kc + k) * DD + n0 + n4 * 4);
            *(float4*)(Bs + k * 64 + n4 * 4) = v;
        }
        __syncthreads();
#pragma unroll 8
        for (int k = 0; k < 64; k++) {
            float4 a = *(const float4*)(As + k * 64 + ty * 4);
            float4 b = *(const float4*)(Bs + k * 64 + tx * 4);
            acc[0][0] += a.x * b.x; acc[0][1] += a.x * b.y; acc[0][2] += a.x * b.z; acc[0][3] += a.x * b.w;
            acc[1][0] += a.y * b.x; acc[1][1] += a.y * b.y; acc[1][2] += a.y * b.z; acc[1][3] += a.y * b.w;
            acc[2][0] += a.z * b.x; acc[2][1] += a.z * b.y; acc[2][2] += a.z * b.z; acc[2][3] += a.z * b.w;
            acc[3][0] += a.w * b.x; acc[3][1] += a.w * b.y; acc[3][2] += a.w * b.z; acc[3][3] += a.w * b.w;
        }
        __syncthreads();
    }
#pragma unroll
    for (int q = 0; q < 4; q++) {
        int r = i0 + ty * 4 + q;
#pragma unroll
        for (int p = 0; p < 4; p++) {
            int n = n0 + tx * 4 + p;
            C[(size_t)r * DD + n] = acc[q][p] + bias[n];
        }
    }
}

// ---------------- 5) normalize -> F1R (fp32) + F1bf (bf16) ----------------
__global__ void k_norm() {
    int row = blockIdx.x * 8 + (threadIdx.x >> 5);
    int lane = threadIdx.x & 31;
    const float4* src = (const float4*)(g_Hx + (size_t)row * DD);
    float4 x0 = src[lane];
    float4 x1 = src[lane + 32];
    float s = x0.x * x0.x + x0.y * x0.y + x0.z * x0.z + x0.w * x0.w
            + x1.x * x1.x + x1.y * x1.y + x1.z * x1.z + x1.w * x1.w;
#pragma unroll
    for (int o = 16; o > 0; o >>= 1) s += __shfl_xor_sync(0xffffffffu, s, o);
    float inv = 1.f / fmaxf(sqrtf(s), 1e-12f);
    float4 y0 = make_float4(x0.x * inv, x0.y * inv, x0.z * inv, x0.w * inv);
    float4 y1 = make_float4(x1.x * inv, x1.y * inv, x1.z * inv, x1.w * inv);
    ((float4*)(g_F1R + (size_t)row * DD))[lane]      = y0;
    ((float4*)(g_F1R + (size_t)row * DD))[lane + 32] = y1;
    __nv_bfloat162* db = (__nv_bfloat162*)(g_F1bf + (size_t)row * DD);
    db[lane * 2]     = __nv_bfloat162(__float2bfloat16(y0.x), __float2bfloat16(y0.y));
    db[lane * 2 + 1] = __nv_bfloat162(__float2bfloat16(y0.z), __float2bfloat16(y0.w));
    db[64 + lane * 2]     = __nv_bfloat162(__float2bfloat16(y1.x), __float2bfloat16(y1.y));
    db[64 + lane * 2 + 1] = __nv_bfloat162(__float2bfloat16(y1.z), __float2bfloat16(y1.w));
}

__device__ __forceinline__ float affinity(float d) {
    d = fminf(fmaxf(d, -1.f), 1.f);
    float sam = acosf(d);
    float e = expf(-0.2f * sam);
    float a = 1.f / (1.f + expf(-e));
    return fmaxf(a, 0.1f);
}

__device__ __forceinline__ void mma_bf16(float c[4], const u32 a[4], const u32 b[2]) {
    asm volatile(
        "mma.sync.aligned.m16n8k16.row.col.f32.bf16.bf16.f32 "
        "{%0,%1,%2,%3}, {%4,%5,%6,%7}, {%8,%9}, {%0,%1,%2,%3};"
        : "+f"(c[0]), "+f"(c[1]), "+f"(c[2]), "+f"(c[3])
        : "r"(a[0]), "r"(a[1]), "r"(a[2]), "r"(a[3]), "r"(b[0]), "r"(b[1]));
}

__device__ __forceinline__ void ldsm4(u32& r0, u32& r1, u32& r2, u32& r3, u32 addr) {
    asm volatile("ldmatrix.sync.aligned.m8n8.x4.shared.b16 {%0,%1,%2,%3}, [%4];"
                 : "=r"(r0), "=r"(r1), "=r"(r2), "=r"(r3) : "r"(addr));
}

__device__ __forceinline__ void cp16(u32 dst, const void* src) {
    asm volatile("cp.async.cg.shared.global [%0], [%1], 16;" :: "r"(dst), "l"(src));
}

// ---------------- 6) main: bf16 HMMA + ldmatrix, fused top-8 + exact rescue ----------------
__global__ __launch_bounds__(256, 1) void k_maintc() {
    extern __shared__ char smem[];
    u32 sb = (u32)__cvta_generic_to_shared(smem);
    u32 fi_u  = sb;
    u32 fja_u = sb + FI_BYTES;
    u32 fjb_u = fja_u + FJ_BYTES;
    float* Ss = (float*)(smem + FI_BYTES + 2 * FJ_BYTES);

    int tid = threadIdx.x;
    int lane = tid & 31, w = tid >> 5;
    int wm = w & 1, wn = w >> 1;           // 2 x 4 warps over 64 x 256
    int gid = lane >> 2, tig = lane & 3;
    int quad = lane >> 3;
    int qr = (quad & 1) * 8 + (lane & 7);  // ldmatrix row offset within 16
    int qc = (quad >> 1) * 8;              // ldmatrix k offset within 16
    int i0 = blockIdx.x * RT;
    int srow = tid >> 2, ssub = tid & 3;   // scan: 4 threads per row

    // load Fi: 64 rows x 512B, row-major, pitch 528
#pragma unroll
    for (int it = 0; it < 8; it++) {
        int e = it * 256 + tid;
        int r = e >> 5, c = e & 31;
        uint4 v = *(const uint4*)((const char*)g_F1bf + (size_t)(i0 + r) * 512 + c * 16);
        *(uint4*)(smem + r * FI_PITCH + c * 16) = v;
    }

    float dv[TOPC]; int dj[TOPC];
#pragma unroll
    for (int m = 0; m < TOPC; m++) { dv[m] = -3.f; dj[m] = 0x7fffffff; }

    // prefetch chunk 0 (j-tile 0) into buffer A
#pragma unroll
    for (int it = 0; it < 8; it++) {
        int e = it * 256 + tid;
        int r = e >> 3, c = e & 7;
        cp16(fja_u + r * FJ_PITCH + c * 16,
             (const char*)g_F1bf + (size_t)r * 512 + c * 16);
    }
    asm volatile("cp.async.commit_group;");
    __syncthreads();

    for (int jt = 0; jt < NJT; jt++) {
        int j0 = jt * JT;
        float acc[2][8][4];
#pragma unroll
        for (int mi = 0; mi < 2; mi++)
#pragma unroll
            for (int ni = 0; ni < 8; ni++)
#pragma unroll
                for (int q = 0; q < 4; q++) acc[mi][ni][q] = 0.f;

        for (int ch = 0; ch < NCH; ch++) {
            int g = jt * NCH + ch;
            bool have_next = (g + 1) < (NJT * NCH);
            if (have_next) {
                int gn = g + 1;
                int njt = gn >> 2, nch = gn & 3;
                int nj0 = njt * JT;
                u32 dstu = (gn & 1) ? fjb_u : fja_u;
#pragma unroll
                for (int it = 0; it < 8; it++) {
                    int e = it * 256 + tid;
                    int r = e >> 3, c = e & 7;
                    cp16(dstu + r * FJ_PITCH + c * 16,
                         (const char*)g_F1bf + (size_t)(nj0 + r) * 512 + nch * 128 + c * 16);
                }
                asm volatile("cp.async.commit_group;");
                asm volatile("cp.async.wait_group 1;");
            } else {
                asm volatile("cp.async.wait_group 0;");
            }
            __syncthreads();

            u32 fj_u = (g & 1) ? fjb_u : fja_u;
#pragma unroll
            for (int s = 0; s < KC / 16; s++) {
                int kA = ch * KC + s * 16;      // global k for Fi
                int kB = s * 16;                // local k in Fj chunk
                u32 a[2][4], b[8][2];
#pragma unroll
                for (int mi = 0; mi < 2; mi++) {
                    u32 addr = fi_u + (u32)((wm * 32 + mi * 16 + qr) * FI_PITCH + (kA + qc) * 2);
                    ldsm4(a[mi][0], a[mi][1], a[mi][2], a[mi][3], addr);
                }
#pragma unroll
                for (int p = 0; p < 4; p++) {
                    u32 addr = fj_u + (u32)((wn * 64 + p * 16 + qr) * FJ_PITCH + (kB + qc) * 2);
                    u32 r0, r1, r2, r3;
                    ldsm4(r0, r1, r2, r3, addr);
                    b[2 * p][0] = r0; b[2 * p + 1][0] = r1;
                    b[2 * p][1] = r2; b[2 * p + 1][1] = r3;
                }
#pragma unroll
                for (int mi = 0; mi < 2; mi++)
#pragma unroll
                    for (int ni = 0; ni < 8; ni++)
                        mma_bf16(acc[mi][ni], a[mi], b[ni]);
            }
            __syncthreads();
        }

        // stage S tile (64 x 256)
#pragma unroll
        for (int mi = 0; mi < 2; mi++) {
            int r = wm * 32 + mi * 16 + gid;
#pragma unroll
            for (int ni = 0; ni < 8; ni++) {
                int c = wn * 64 + ni * 8 + tig * 2;
                *(float2*)(Ss + r * S_PAD + c)       = make_float2(acc[mi][ni][0], acc[mi][ni][1]);
                *(float2*)(Ss + (r + 8) * S_PAD + c) = make_float2(acc[mi][ni][2], acc[mi][ni][3]);
            }
        }
        __syncthreads();

        // scan: 4 threads/row, cols c = ii*4 + ssub ascending
#pragma unroll 8
        for (int ii = 0; ii < 64; ii++) {
            int c = ii * 4 + ssub;
            float v = Ss[srow * S_PAD + c];
            int jj = j0 + c;
            if (v > dv[TOPC - 1] || (v == dv[TOPC - 1] && jj < dj[TOPC - 1])) {
                dv[TOPC - 1] = v; dj[TOPC - 1] = jj;
#pragma unroll
                for (int m = TOPC - 1; m > 0; m--) {
                    bool sw = dv[m] > dv[m - 1] || (dv[m] == dv[m - 1] && dj[m] < dj[m - 1]);
                    if (sw) {
                        float tf = dv[m]; dv[m] = dv[m - 1]; dv[m - 1] = tf;
                        int ti = dj[m]; dj[m] = dj[m - 1]; dj[m - 1] = ti;
                    }
                }
            }
        }
        __syncthreads();
    }

    // ---- merge 4 scan-threads per row, then exact fp32 rescue ----
    float* cv = Ss;                   // [64][32]
    int*   cj = (int*)(Ss + 64 * 32); // [64][32]
#pragma unroll
    for (int m = 0; m < TOPC; m++) {
        cv[srow * 32 + ssub * TOPC + m] = dv[m];
        cj[srow * 32 + ssub * TOPC + m] = dj[m];
    }
    __syncthreads();

    if (tid < RT) {
        int i = i0 + tid;
        float mv[TOPC]; int mj[TOPC];
#pragma unroll
        for (int m = 0; m < TOPC; m++) { mv[m] = -3.f; mj[m] = 0x7fffffff; }
        for (int c = 0; c < 32; c++) {
            float v = cv[tid * 32 + c];
            int jj = cj[tid * 32 + c];
            if (v > mv[TOPC - 1] || (v == mv[TOPC - 1] && jj < mj[TOPC - 1])) {
                mv[TOPC - 1] = v; mj[TOPC - 1] = jj;
#pragma unroll
                for (int m = TOPC - 1; m > 0; m--) {
                    bool sw = mv[m] > mv[m - 1] || (mv[m] == mv[m - 1] && mj[m] < mj[m - 1]);
                    if (sw) {
                        float tf = mv[m]; mv[m] = mv[m - 1]; mv[m - 1] = tf;
                        int ti = mj[m]; mj[m] = mj[m - 1]; mj[m - 1] = ti;
                    }
                }
            }
        }

        // exact fp32 dots (sequential-k chains — identical to all passing rounds)
        float ev[TOPC];
#pragma unroll
        for (int m = 0; m < TOPC; m++) ev[m] = 0.f;
        const float* ri = g_F1R + (size_t)i * DD;
        for (int k = 0; k < DD; k++) {
            float a = ri[k];
#pragma unroll
            for (int m = 0; m < TOPC; m++)
                ev[m] = fmaf(a, g_F1R[(size_t)mj[m] * DD + k], ev[m]);
        }

        // sort by (exact dot desc, idx asc)
#pragma unroll
        for (int m = 1; m < TOPC; m++) {
#pragma unroll
            for (int q = TOPC - 1; q >= 1; q--) {
                bool sw = (ev[q] > ev[q - 1]) || (ev[q] == ev[q - 1] && mj[q] < mj[q - 1]);
                if (sw) {
                    float tf = ev[q]; ev[q] = ev[q - 1]; ev[q - 1] = tf;
                    int ti = mj[q]; mj[q] = mj[q - 1]; mj[q - 1] = ti;
                }
            }
        }

        // A values + stable (A desc, idx asc) sort — matches lax.top_k ties
        float av[TOPC];
#pragma unroll
        for (int m = 0; m < TOPC; m++) av[m] = affinity(ev[m]);
#pragma unroll
        for (int m = 1; m < TOPC; m++) {
#pragma unroll
            for (int q = TOPC - 1; q >= 1; q--) {
                bool sw = (av[q] > av[q - 1]) || (av[q] == av[q - 1] && mj[q] < mj[q - 1]);
                if (sw) {
                    float tf = av[q]; av[q] = av[q - 1]; av[q - 1] = tf;
                    int ti = mj[q]; mj[q] = mj[q - 1]; mj[q - 1] = ti;
                }
            }
        }

        float rs = 0.f;
#pragma unroll
        for (int q = 0; q < TK; q++) {
            rs += av[q];
            g_tv[i * TK + q] = av[q];
            g_ti[i * TK + q] = mj[q];
        }
        g_dinv[i] = rsqrtf(rs);
    }
}

// ---------------- 7) scatter sparse A ----------------
__global__ void k_scatterA(float* __restrict__ A) {
    int e = blockIdx.x * blockDim.x + threadIdx.x;
    if (e < NN * TK) {
        int row = e / TK;
        A[(size_t)row * NN + g_ti[e]] = g_tv[e];
    }
}

// ---------------- 8) out = leaky(A_hat @ G) ----------------
__global__ void k_out(float* __restrict__ out) {
    int i = blockIdx.x;
    int c4 = threadIdx.x;
    float di = g_dinv[i];
    float4 acc = make_float4(0.f, 0.f, 0.f, 0.f);
#pragma unroll
    for (int q = 0; q < TK; q++) {
        int j = g_ti[i * TK + q];
        float w = di * g_tv[i * TK + q] * g_dinv[j];
        float4 g = ((const float4*)(g_G + (size_t)j * DD))[c4];
        acc.x += w * g.x; acc.y += w * g.y; acc.z += w * g.z; acc.w += w * g.w;
    }
    acc.x = acc.x >= 0.f ? acc.x : 0.01f * acc.x;
    acc.y = acc.y >= 0.f ? acc.y : 0.01f * acc.y;
    acc.z = acc.z >= 0.f ? acc.z : 0.01f * acc.z;
    acc.w = acc.w >= 0.f ? acc.w : 0.01f * acc.w;
    ((float4*)(out + (size_t)i * DD))[c4] = acc;
}

// ---------------- launcher ----------------
extern "C" void kernel_launch(void* const* d_in, const int* in_sizes, int n_in,
                              void* d_out, int out_size) {
    const float* H     = (const float*)d_in[0];
    const float* gamma = (const float*)d_in[1];
    const float* beta  = (const float*)d_in[2];
    const float* Wt    = (const float*)d_in[3];
    const float* bt    = (const float*)d_in[4];
    const float* Wo    = (const float*)d_in[5];
    const float* bo    = (const float*)d_in[6];

    float* outbuf = (float*)d_out;
    const long long OUT_ND = (long long)NN * DD;
    const long long A_NN   = (long long)NN * NN;

    float* outp = nullptr;
    float* Ap   = nullptr;
    long long osz = (long long)out_size;
    if (osz == OUT_ND + A_NN)      { outp = outbuf; Ap = outbuf + OUT_ND; }
    else if (osz == A_NN)          { Ap = outbuf; }
    else if (osz == OUT_ND)        { outp = outbuf; }
    else                           { outp = outbuf; if (osz >= OUT_ND + A_NN) Ap = outbuf + OUT_ND; }

    const int main_smem = FI_BYTES + 2 * FJ_BYTES + RT * S_PAD * 4;  // 175104
    cudaFuncSetAttribute(k_maintc, cudaFuncAttributeMaxDynamicSharedMemorySize, main_smem);

    k_stats1<<<32, 256>>>(H);
    k_stats2<<<1, 256>>>(gamma, beta);
    k_hnT<<<NN / 32, 256>>>(H);
    {
        dim3 g(NN / 64, 8);
        k_gemm<<<g, 256>>>(Wt, bt, Wo, bo);
    }
    k_norm<<<NN / 8, 256>>>();
    k_maintc<<<NN / RT, 256, main_smem>>>();

    if (Ap) {
        cudaMemsetAsync(Ap, 0, (size_t)A_NN * sizeof(float), 0);
        k_scatterA<<<(NN * TK + 255) / 256, 256>>>(Ap);
    }
    if (outp) {
        k_out<<<NN, 64>>>(outp);
    }
}

// round 9
// speedup vs baseline: 1.7339x; 1.1110x over previous
#include <cuda_runtime.h>
#include <cuda_bf16.h>
#include <math.h>

typedef unsigned int u32;

#define NN 8192
#define DD 256
#define TK 5
#define TOPC 8

#define RT 64        // rows per CTA
#define JT 256       // j tile
#define KC 64        // k chunk (bf16) for Fj
#define NCH (DD / KC)     // 4
#define NJT (NN / JT)     // 32
#define FI_PITCH 528      // bytes/row, 33*16 -> ldmatrix conflict-free
#define FJ_PITCH 144      // bytes/row, 9*16  -> ldmatrix conflict-free
#define FI_BYTES (RT * FI_PITCH)       // 33792
#define FJ_BYTES (JT * FJ_PITCH)       // 36864
#define S_PAD 264
#define NT 512       // threads per CTA (16 warps)

// ---------------- device scratch ----------------
__device__ float g_psum[32][DD];
__device__ float g_psq[32][DD];
__device__ float g_scale[DD];
__device__ float g_shift[DD];
__device__ float g_HnT[DD * NN];
__device__ float g_Hx[NN * DD];
__device__ float g_F1R[NN * DD];            // exact fp32 normalized rows
__device__ __nv_bfloat16 g_F1bf[NN * DD];   // bf16 rows (mma operands)
__device__ float g_G[NN * DD];
__device__ float g_tv[NN * TK];
__device__ int   g_ti[NN * TK];
__device__ float g_dinv[NN];

// ---------------- 1) batchnorm stats ----------------
__global__ void k_stats1(const float* __restrict__ H) {
    int b = blockIdx.x, t = threadIdx.x;
    const float* p = H + (size_t)b * 256 * DD + t;
    float s = 0.f, q = 0.f;
#pragma unroll 8
    for (int r = 0; r < 256; r++) {
        float x = p[(size_t)r * DD];
        s += x; q += x * x;
    }
    g_psum[b][t] = s;
    g_psq[b][t]  = q;
}

__global__ void k_stats2(const float* __restrict__ gamma, const float* __restrict__ beta) {
    int t = threadIdx.x;
    float s = 0.f, q = 0.f;
    for (int b = 0; b < 32; b++) { s += g_psum[b][t]; q += g_psq[b][t]; }
    float mu  = s * (1.f / NN);
    float var = q * (1.f / NN) - mu * mu;
    float sc  = gamma[t] * rsqrtf(var + 1e-5f);
    g_scale[t] = sc;
    g_shift[t] = beta[t] - mu * sc;
}

// ---------------- 3) Hn transposed [k][row] ----------------
__global__ void k_hnT(const float* __restrict__ H) {
    __shared__ float buf[32 * 257];
    int r0 = blockIdx.x * 32;
    int tid = threadIdx.x;
#pragma unroll
    for (int it = 0; it < 8; it++) {
        int e = it * 256 + tid;
        int r = e >> 6;
        int c = (e & 63) * 4;
        float4 h = *(const float4*)(H + (size_t)(r0 + r) * DD + c);
        buf[r * 257 + c + 0] = fmaf(h.x, g_scale[c + 0], g_shift[c + 0]);
        buf[r * 257 + c + 1] = fmaf(h.y, g_scale[c + 1], g_shift[c + 1]);
        buf[r * 257 + c + 2] = fmaf(h.z, g_scale[c + 2], g_shift[c + 2]);
        buf[r * 257 + c + 3] = fmaf(h.w, g_scale[c + 3], g_shift[c + 3]);
    }
    __syncthreads();
    int lane = tid & 31;
    int cbase = tid >> 5;
#pragma unroll
    for (int it = 0; it < 32; it++) {
        int c = cbase + it * 8;
        g_HnT[(size_t)c * NN + r0 + lane] = buf[lane * 257 + c];
    }
}

// ---------------- 4) GEMM: [Hx | G] ----------------
__global__ __launch_bounds__(256) void k_gemm(
    const float* __restrict__ Wt, const float* __restrict__ bt,
    const float* __restrict__ Wo, const float* __restrict__ bo) {
    __shared__ float As[64 * 64];
    __shared__ float Bs[64 * 64];
    int tid = threadIdx.x, tx = tid & 15, ty = tid >> 4;
    int i0 = blockIdx.x * 64;
    int by = blockIdx.y;
    const float* W    = (by < 4) ? Wt : Wo;
    const float* bias = (by < 4) ? bt : bo;
    float* C          = (by < 4) ? g_Hx : g_G;
    int n0 = (by & 3) * 64;

    float acc[4][4] = {};
    for (int kc = 0; kc < 256; kc += 64) {
#pragma unroll
        for (int it = 0; it < 4; it++) {
            int e = it * 256 + tid;
            int k = e >> 4, r4 = e & 15;
            float4 v = *(const float4*)(g_HnT + (size_t)(kc + k) * NN + i0 + r4 * 4);
            *(float4*)(As + k * 64 + r4 * 4) = v;
        }
#pragma unroll
        for (int it = 0; it < 4; it++) {
            int e = it * 256 + tid;
            int k = e >> 4, n4 = e & 15;
            float4 v = *(const float4*)(W + (size_t)(kc + k) * DD + n0 + n4 * 4);
            *(float4*)(Bs + k * 64 + n4 * 4) = v;
        }
        __syncthreads();
#pragma unroll 8
        for (int k = 0; k < 64; k++) {
            float4 a = *(const float4*)(As + k * 64 + ty * 4);
            float4 b = *(const float4*)(Bs + k * 64 + tx * 4);
            acc[0][0] += a.x * b.x; acc[0][1] += a.x * b.y; acc[0][2] += a.x * b.z; acc[0][3] += a.x * b.w;
            acc[1][0] += a.y * b.x; acc[1][1] += a.y * b.y; acc[1][2] += a.y * b.z; acc[1][3] += a.y * b.w;
            acc[2][0] += a.z * b.x; acc[2][1] += a.z * b.y; acc[2][2] += a.z * b.z; acc[2][3] += a.z * b.w;
            acc[3][0] += a.w * b.x; acc[3][1] += a.w * b.y; acc[3][2] += a.w * b.z; acc[3][3] += a.w * b.w;
        }
        __syncthreads();
    }
#pragma unroll
    for (int q = 0; q < 4; q++) {
        int r = i0 + ty * 4 + q;
#pragma unroll
        for (int p = 0; p < 4; p++) {
            int n = n0 + tx * 4 + p;
            C[(size_t)r * DD + n] = acc[q][p] + bias[n];
        }
    }
}

// ---------------- 5) normalize -> F1R (fp32) + F1bf (bf16) ----------------
__global__ void k_norm() {
    int row = blockIdx.x * 8 + (threadIdx.x >> 5);
    int lane = threadIdx.x & 31;
    const float4* src = (const float4*)(g_Hx + (size_t)row * DD);
    float4 x0 = src[lane];
    float4 x1 = src[lane + 32];
    float s = x0.x * x0.x + x0.y * x0.y + x0.z * x0.z + x0.w * x0.w
            + x1.x * x1.x + x1.y * x1.y + x1.z * x1.z + x1.w * x1.w;
#pragma unroll
    for (int o = 16; o > 0; o >>= 1) s += __shfl_xor_sync(0xffffffffu, s, o);
    float inv = 1.f / fmaxf(sqrtf(s), 1e-12f);
    float4 y0 = make_float4(x0.x * inv, x0.y * inv, x0.z * inv, x0.w * inv);
    float4 y1 = make_float4(x1.x * inv, x1.y * inv, x1.z * inv, x1.w * inv);
    ((float4*)(g_F1R + (size_t)row * DD))[lane]      = y0;
    ((float4*)(g_F1R + (size_t)row * DD))[lane + 32] = y1;
    __nv_bfloat162* db = (__nv_bfloat162*)(g_F1bf + (size_t)row * DD);
    db[lane * 2]     = __nv_bfloat162(__float2bfloat16(y0.x), __float2bfloat16(y0.y));
    db[lane * 2 + 1] = __nv_bfloat162(__float2bfloat16(y0.z), __float2bfloat16(y0.w));
    db[64 + lane * 2]     = __nv_bfloat162(__float2bfloat16(y1.x), __float2bfloat16(y1.y));
    db[64 + lane * 2 + 1] = __nv_bfloat162(__float2bfloat16(y1.z), __float2bfloat16(y1.w));
}

__device__ __forceinline__ float affinity(float d) {
    d = fminf(fmaxf(d, -1.f), 1.f);
    float sam = acosf(d);
    float e = expf(-0.2f * sam);
    float a = 1.f / (1.f + expf(-e));
    return fmaxf(a, 0.1f);
}

__device__ __forceinline__ void mma_bf16(float c[4], const u32 a[4], const u32 b[2]) {
    asm volatile(
        "mma.sync.aligned.m16n8k16.row.col.f32.bf16.bf16.f32 "
        "{%0,%1,%2,%3}, {%4,%5,%6,%7}, {%8,%9}, {%0,%1,%2,%3};"
        : "+f"(c[0]), "+f"(c[1]), "+f"(c[2]), "+f"(c[3])
        : "r"(a[0]), "r"(a[1]), "r"(a[2]), "r"(a[3]), "r"(b[0]), "r"(b[1]));
}

__device__ __forceinline__ void ldsm4(u32& r0, u32& r1, u32& r2, u32& r3, u32 addr) {
    asm volatile("ldmatrix.sync.aligned.m8n8.x4.shared.b16 {%0,%1,%2,%3}, [%4];"
                 : "=r"(r0), "=r"(r1), "=r"(r2), "=r"(r3) : "r"(addr));
}

__device__ __forceinline__ void cp16(u32 dst, const void* src) {
    asm volatile("cp.async.cg.shared.global [%0], [%1], 16;" :: "r"(dst), "l"(src));
}

// ---------------- 6) main: bf16 HMMA, 16 warps, fused top-8 + exact rescue ----------------
__global__ __launch_bounds__(NT, 1) void k_maintc() {
    extern __shared__ char smem[];
    u32 sb = (u32)__cvta_generic_to_shared(smem);
    u32 fi_u  = sb;
    u32 fja_u = sb + FI_BYTES;
    u32 fjb_u = fja_u + FJ_BYTES;
    float* Ss = (float*)(smem + FI_BYTES + 2 * FJ_BYTES);

    int tid = threadIdx.x;
    int lane = tid & 31, w = tid >> 5;
    int wm = w & 3, wn = w >> 2;           // 4 x 4 warps over 64 x 256
    int gid = lane >> 2, tig = lane & 3;
    int quad = lane >> 3;
    int qr = (quad & 1) * 8 + (lane & 7);  // ldmatrix row offset within 16
    int qc = (quad >> 1) * 8;              // ldmatrix k offset within 16
    int i0 = blockIdx.x * RT;
    int srow = tid >> 3, ssub = tid & 7;   // scan: 8 threads per row

    // load Fi: 64 rows x 512B, row-major, pitch 528
#pragma unroll
    for (int it = 0; it < 4; it++) {
        int e = it * NT + tid;
        int r = e >> 5, c = e & 31;
        uint4 v = *(const uint4*)((const char*)g_F1bf + (size_t)(i0 + r) * 512 + c * 16);
        *(uint4*)(smem + r * FI_PITCH + c * 16) = v;
    }

    float dv[TOPC]; int dj[TOPC];
#pragma unroll
    for (int m = 0; m < TOPC; m++) { dv[m] = -3.f; dj[m] = 0x7fffffff; }

    // prefetch chunk 0 (j-tile 0) into buffer A
#pragma unroll
    for (int it = 0; it < 4; it++) {
        int e = it * NT + tid;
        int r = e >> 3, c = e & 7;
        cp16(fja_u + r * FJ_PITCH + c * 16,
             (const char*)g_F1bf + (size_t)r * 512 + c * 16);
    }
    asm volatile("cp.async.commit_group;");
    __syncthreads();

    for (int jt = 0; jt < NJT; jt++) {
        int j0 = jt * JT;
        float acc[8][4];
#pragma unroll
        for (int ni = 0; ni < 8; ni++)
#pragma unroll
            for (int q = 0; q < 4; q++) acc[ni][q] = 0.f;

        for (int ch = 0; ch < NCH; ch++) {
            int g = jt * NCH + ch;
            bool have_next = (g + 1) < (NJT * NCH);
            if (have_next) {
                int gn = g + 1;
                int njt = gn >> 2, nch = gn & 3;
                int nj0 = njt * JT;
                u32 dstu = (gn & 1) ? fjb_u : fja_u;
#pragma unroll
                for (int it = 0; it < 4; it++) {
                    int e = it * NT + tid;
                    int r = e >> 3, c = e & 7;
                    cp16(dstu + r * FJ_PITCH + c * 16,
                         (const char*)g_F1bf + (size_t)(nj0 + r) * 512 + nch * 128 + c * 16);
                }
                asm volatile("cp.async.commit_group;");
                asm volatile("cp.async.wait_group 1;");
            } else {
                asm volatile("cp.async.wait_group 0;");
            }
            __syncthreads();

            u32 fj_u = (g & 1) ? fjb_u : fja_u;
#pragma unroll
            for (int s = 0; s < KC / 16; s++) {
                int kA = ch * KC + s * 16;      // global k for Fi
                int kB = s * 16;                // local k in Fj chunk
                u32 a[4], b[8][2];
                {
                    u32 addr = fi_u + (u32)((wm * 16 + qr) * FI_PITCH + (kA + qc) * 2);
                    ldsm4(a[0], a[1], a[2], a[3], addr);
                }
#pragma unroll
                for (int p = 0; p < 4; p++) {
                    u32 addr = fj_u + (u32)((wn * 64 + p * 16 + qr) * FJ_PITCH + (kB + qc) * 2);
                    u32 r0, r1, r2, r3;
                    ldsm4(r0, r1, r2, r3, addr);
                    b[2 * p][0] = r0; b[2 * p + 1][0] = r1;
                    b[2 * p][1] = r2; b[2 * p + 1][1] = r3;
                }
#pragma unroll
                for (int ni = 0; ni < 8; ni++)
                    mma_bf16(acc[ni], a, b[ni]);
            }
            __syncthreads();
        }

        // stage S tile (64 x 256)
        {
            int r = wm * 16 + gid;
#pragma unroll
            for (int ni = 0; ni < 8; ni++) {
                int c = wn * 64 + ni * 8 + tig * 2;
                *(float2*)(Ss + r * S_PAD + c)       = make_float2(acc[ni][0], acc[ni][1]);
                *(float2*)(Ss + (r + 8) * S_PAD + c) = make_float2(acc[ni][2], acc[ni][3]);
            }
        }
        __syncthreads();

        // scan: 8 threads/row, cols c = ii*8 + ssub ascending
#pragma unroll 8
        for (int ii = 0; ii < 32; ii++) {
            int c = ii * 8 + ssub;
            float v = Ss[srow * S_PAD + c];
            int jj = j0 + c;
            if (v > dv[TOPC - 1] || (v == dv[TOPC - 1] && jj < dj[TOPC - 1])) {
                dv[TOPC - 1] = v; dj[TOPC - 1] = jj;
#pragma unroll
                for (int m = TOPC - 1; m > 0; m--) {
                    bool sw = dv[m] > dv[m - 1] || (dv[m] == dv[m - 1] && dj[m] < dj[m - 1]);
                    if (sw) {
                        float tf = dv[m]; dv[m] = dv[m - 1]; dv[m - 1] = tf;
                        int ti = dj[m]; dj[m] = dj[m - 1]; dj[m - 1] = ti;
                    }
                }
            }
        }
        __syncthreads();
    }

    // ---- merge 8 scan-threads per row, then exact fp32 rescue ----
    float* cv = Ss;                   // [64][64]
    int*   cj = (int*)(Ss + 64 * 64); // [64][64]
#pragma unroll
    for (int m = 0; m < TOPC; m++) {
        cv[srow * 64 + ssub * TOPC + m] = dv[m];
        cj[srow * 64 + ssub * TOPC + m] = dj[m];
    }
    __syncthreads();

    if (tid < RT) {
        int i = i0 + tid;
        float mv[TOPC]; int mj[TOPC];
#pragma unroll
        for (int m = 0; m < TOPC; m++) { mv[m] = -3.f; mj[m] = 0x7fffffff; }
        for (int c = 0; c < 64; c++) {
            float v = cv[tid * 64 + c];
            int jj = cj[tid * 64 + c];
            if (v > mv[TOPC - 1] || (v == mv[TOPC - 1] && jj < mj[TOPC - 1])) {
                mv[TOPC - 1] = v; mj[TOPC - 1] = jj;
#pragma unroll
                for (int m = TOPC - 1; m > 0; m--) {
                    bool sw = mv[m] > mv[m - 1] || (mv[m] == mv[m - 1] && mj[m] < mj[m - 1]);
                    if (sw) {
                        float tf = mv[m]; mv[m] = mv[m - 1]; mv[m - 1] = tf;
                        int ti = mj[m]; mj[m] = mj[m - 1]; mj[m - 1] = ti;
                    }
                }
            }
        }

        // exact fp32 dots (sequential-k chains — identical to all passing rounds)
        float ev[TOPC];
#pragma unroll
        for (int m = 0; m < TOPC; m++) ev[m] = 0.f;
        const float* ri = g_F1R + (size_t)i * DD;
        for (int k = 0; k < DD; k++) {
            float a = ri[k];
#pragma unroll
            for (int m = 0; m < TOPC; m++)
                ev[m] = fmaf(a, g_F1R[(size_t)mj[m] * DD + k], ev[m]);
        }

        // sort by (exact dot desc, idx asc)
#pragma unroll
        for (int m = 1; m < TOPC; m++) {
#pragma unroll
            for (int q = TOPC - 1; q >= 1; q--) {
                bool sw = (ev[q] > ev[q - 1]) || (ev[q] == ev[q - 1] && mj[q] < mj[q - 1]);
                if (sw) {
                    float tf = ev[q]; ev[q] = ev[q - 1]; ev[q - 1] = tf;
                    int ti = mj[q]; mj[q] = mj[q - 1]; mj[q - 1] = ti;
                }
            }
        }

        // A values + stable (A desc, idx asc) sort — matches lax.top_k ties
        float av[TOPC];
#pragma unroll
        for (int m = 0; m < TOPC; m++) av[m] = affinity(ev[m]);
#pragma unroll
        for (int m = 1; m < TOPC; m++) {
#pragma unroll
            for (int q = TOPC - 1; q >= 1; q--) {
                bool sw = (av[q] > av[q - 1]) || (av[q] == av[q - 1] && mj[q] < mj[q - 1]);
                if (sw) {
                    float tf = av[q]; av[q] = av[q - 1]; av[q - 1] = tf;
                    int ti = mj[q]; mj[q] = mj[q - 1]; mj[q - 1] = ti;
                }
            }
        }

        float rs = 0.f;
#pragma unroll
        for (int q = 0; q < TK; q++) {
            rs += av[q];
            g_tv[i * TK + q] = av[q];
            g_ti[i * TK + q] = mj[q];
        }
        g_dinv[i] = rsqrtf(rs);
    }
}

// ---------------- 7) scatter sparse A ----------------
__global__ void k_scatterA(float* __restrict__ A) {
    int e = blockIdx.x * blockDim.x + threadIdx.x;
    if (e < NN * TK) {
        int row = e / TK;
        A[(size_t)row * NN + g_ti[e]] = g_tv[e];
    }
}

// ---------------- 8) out = leaky(A_hat @ G) ----------------
__global__ void k_out(float* __restrict__ out) {
    int i = blockIdx.x;
    int c4 = threadIdx.x;
    float di = g_dinv[i];
    float4 acc = make_float4(0.f, 0.f, 0.f, 0.f);
#pragma unroll
    for (int q = 0; q < TK; q++) {
        int j = g_ti[i * TK + q];
        float w = di * g_tv[i * TK + q] * g_dinv[j];
        float4 g = ((const float4*)(g_G + (size_t)j * DD))[c4];
        acc.x += w * g.x; acc.y += w * g.y; acc.z += w * g.z; acc.w += w * g.w;
    }
    acc.x = acc.x >= 0.f ? acc.x : 0.01f * acc.x;
    acc.y = acc.y >= 0.f ? acc.y : 0.01f * acc.y;
    acc.z = acc.z >= 0.f ? acc.z : 0.01f * acc.z;
    acc.w = acc.w >= 0.f ? acc.w : 0.01f * acc.w;
    ((float4*)(out + (size_t)i * DD))[c4] = acc;
}

// ---------------- launcher ----------------
extern "C" void kernel_launch(void* const* d_in, const int* in_sizes, int n_in,
                              void* d_out, int out_size) {
    const float* H     = (const float*)d_in[0];
    const float* gamma = (const float*)d_in[1];
    const float* beta  = (const float*)d_in[2];
    const float* Wt    = (const float*)d_in[3];
    const float* bt    = (const float*)d_in[4];
    const float* Wo    = (const float*)d_in[5];
    const float* bo    = (const float*)d_in[6];

    float* outbuf = (float*)d_out;
    const long long OUT_ND = (long long)NN * DD;
    const long long A_NN   = (long long)NN * NN;

    float* outp = nullptr;
    float* Ap   = nullptr;
    long long osz = (long long)out_size;
    if (osz == OUT_ND + A_NN)      { outp = outbuf; Ap = outbuf + OUT_ND; }
    else if (osz == A_NN)          { Ap = outbuf; }
    else if (osz == OUT_ND)        { outp = outbuf; }
    else                           { outp = outbuf; if (osz >= OUT_ND + A_NN) Ap = outbuf + OUT_ND; }

    const int main_smem = FI_BYTES + 2 * FJ_BYTES + RT * S_PAD * 4;  // 175104
    cudaFuncSetAttribute(k_maintc, cudaFuncAttributeMaxDynamicSharedMemorySize, main_smem);

    k_stats1<<<32, 256>>>(H);
    k_stats2<<<1, 256>>>(gamma, beta);
    k_hnT<<<NN / 32, 256>>>(H);
    {
        dim3 g(NN / 64, 8);
        k_gemm<<<g, 256>>>(Wt, bt, Wo, bo);
    }
    k_norm<<<NN / 8, 256>>>();
    k_maintc<<<NN / RT, NT, main_smem>>>();

    if (Ap) {
        cudaMemsetAsync(Ap, 0, (size_t)A_NN * sizeof(float), 0);
        k_scatterA<<<(NN * TK + 255) / 256, 256>>>(Ap);
    }
    if (outp) {
        k_out<<<NN, 64>>>(outp);
    }
}